// round 3
// baseline (speedup 1.0000x reference)
#include <cuda_runtime.h>
#include <math.h>

#define NFR 5
#define BB  8
#define CC  64
#define HW  16384
#define KK  320
#define TPX 64          // pixels per k_origin block
#define GX  (HW/TPX)    // 256 blocks in x per batch

typedef unsigned long long ull;

// Scratch (allocation-free rules): partial stats, folded weights, frame partials.
__device__ __align__(16) float g_part[(size_t)BB*GX*768];  // [(b*GX+bx)*768 + c*12 + s]
__device__ float g_A[BB*NFR*CC];
__device__ __align__(16) float g_yp[(size_t)NFR*BB*HW];

__device__ __forceinline__ void fma2(ull &d, ull a, ull b) {
    asm("fma.rn.f32x2 %0, %1, %2, %0;" : "+l"(d) : "l"(a), "l"(b));
}
__device__ __forceinline__ ull pack2(float x) {
    ull r; unsigned u = __float_as_uint(x);
    asm("mov.b64 %0, {%1, %1};" : "=l"(r) : "r"(u));
    return r;
}
__device__ __forceinline__ float lo32(ull a){ return __uint_as_float((unsigned)a); }
__device__ __forceinline__ float hi32(ull a){ return __uint_as_float((unsigned)(a>>32)); }

__device__ __forceinline__ void cp16(void* s, const void* g){
    unsigned saddr = (unsigned)__cvta_generic_to_shared(s);
    asm volatile("cp.async.cg.shared.global [%0], [%1], 16;\n" :: "r"(saddr), "l"(g) : "memory");
}
__device__ __forceinline__ void cp_commit(){ asm volatile("cp.async.commit_group;\n" ::: "memory"); }
__device__ __forceinline__ void cp_wait0(){ asm volatile("cp.async.wait_group 0;\n" ::: "memory"); }

// ---------------------------------------------------------------------------
// K1 fused: origin GEMM (f32x2 packed FMA) + difference-basis stats, all from
// a persistent smem image of this block's 64 pixels x 320 K-rows.
// Emits per-block partial (dot, nrm, dsum) for each (c, f) -> g_part.
// smem: xs[320][64] floats (80KB) + ws2[2][32][65] u64 pre-packed W (32.5KB)
// ---------------------------------------------------------------------------
__global__ __launch_bounds__(128, 2) void k_origin_fused(const float* __restrict__ inp,
                                                         const float* __restrict__ origin_w) {
    extern __shared__ char smem_raw[];
    float* xs = (float*)smem_raw;                              // [320][64]
    ull*   ws2 = (ull*)(smem_raw + (size_t)KK*TPX*4);          // [2][32][65]

    const int tid = threadIdx.x;
    const int b   = blockIdx.y;
    const int bx  = blockIdx.x;
    const int p0  = bx * TPX;
    const int ty  = tid >> 3;        // 0..15 -> 4-channel group
    const int tx  = tid & 7;         // 0..7  -> 8-pixel group
    const int c0  = ty * 4;
    const int pp0 = tx * 4;          // u64 index (pixels tx*8 .. tx*8+7)
    const int kkx = tid & 31;
    const int wrp = tid >> 5;

    ull acc[4][4];
#pragma unroll
    for (int i = 0; i < 4; i++)
#pragma unroll
        for (int j = 0; j < 4; j++) acc[i][j] = 0ull;

    float wv[16];

    // ---- prologue: stage chunk 0 (x via cp.async, W via ld/st packed) ----
#pragma unroll
    for (int it = 0; it < 16; it++) {
        int cch = it * 4 + wrp;
        wv[it] = origin_w[cch * KK + kkx];
    }
#pragma unroll
    for (int it = 0; it < 4; it++) {
        int e = it * 128 + tid;
        int row = e >> 4, col4 = e & 15;
        int f = row >> 6, cp = row & 63;                        // chunk 0: k=row
        cp16(xs + (size_t)row * TPX + col4 * 4,
             inp + (size_t)((f * BB + b) * CC + cp) * HW + p0 + col4 * 4);
    }
    cp_commit();
#pragma unroll
    for (int it = 0; it < 16; it++) {
        int cch = it * 4 + wrp;
        ws2[(size_t)kkx * 65 + cch] = pack2(wv[it]);
    }
    cp_wait0();
    __syncthreads();

    int buf = 0;
    for (int ch = 0; ch < 10; ch++) {
        // stage next chunk (disjoint xs rows; other ws buffer)
        if (ch < 9) {
            int kb = (ch + 1) * 32;
#pragma unroll
            for (int it = 0; it < 16; it++) {
                int cch = it * 4 + wrp;
                wv[it] = origin_w[cch * KK + kb + kkx];
            }
#pragma unroll
            for (int it = 0; it < 4; it++) {
                int e = it * 128 + tid;
                int row = e >> 4, col4 = e & 15;
                int k = kb + row;
                int f = k >> 6, cp = k & 63;
                cp16(xs + (size_t)k * TPX + col4 * 4,
                     inp + (size_t)((f * BB + b) * CC + cp) * HW + p0 + col4 * 4);
            }
            cp_commit();
        }

        // compute chunk ch
        const float* xbase = xs + (size_t)ch * 32 * TPX;
        const ull* wbase = ws2 + (size_t)buf * 32 * 65;
#pragma unroll 4
        for (int kx = 0; kx < 32; kx++) {
            const ull* xrow = (const ull*)(xbase + kx * TPX);
            ulonglong2 xa = *(const ulonglong2*)(xrow + pp0);
            ulonglong2 xb = *(const ulonglong2*)(xrow + pp0 + 2);
            const ull* wrow = wbase + kx * 65;
#pragma unroll
            for (int ci = 0; ci < 4; ci++) {
                ull ww = wrow[c0 + ci];
                fma2(acc[ci][0], ww, xa.x);
                fma2(acc[ci][1], ww, xa.y);
                fma2(acc[ci][2], ww, xb.x);
                fma2(acc[ci][3], ww, xb.y);
            }
        }

        if (ch < 9) {
            ull* wdst = ws2 + (size_t)(buf ^ 1) * 32 * 65;
#pragma unroll
            for (int it = 0; it < 16; it++) {
                int cch = it * 4 + wrp;
                wdst[(size_t)kkx * 65 + cch] = pack2(wv[it]);
            }
            cp_wait0();
        }
        __syncthreads();
        buf ^= 1;
    }

    // ---- fused stats from the persistent image ----
#pragma unroll
    for (int ci = 0; ci < 4; ci++) {
        int c = c0 + ci;
        float o[8];
#pragma unroll
        for (int j = 0; j < 4; j++) { o[2*j] = lo32(acc[ci][j]); o[2*j+1] = hi32(acc[ci][j]); }
        const ull* lrow = (const ull*)(xs + (size_t)(4 * CC + c) * TPX);
        ull L[4];
#pragma unroll
        for (int j = 0; j < 4; j++) L[j] = lrow[pp0 + j];

        float dt[4], nr[4], dsm[4];
#pragma unroll
        for (int f = 0; f < 4; f++) {
            const ull* xr = (const ull*)(xs + (size_t)(f * CC + c) * TPX);
            float d_ = 0.f, n_ = 0.f, s_ = 0.f;
#pragma unroll
            for (int j = 0; j < 4; j++) {
                ull X = xr[pp0 + j];
                float dl = lo32(L[j]) - lo32(X);
                float dh = hi32(L[j]) - hi32(X);
                d_ += o[2*j] * dl + o[2*j+1] * dh;
                n_ += dl * dl + dh * dh;
                s_ += dl + dh;
            }
            dt[f] = d_; nr[f] = n_; dsm[f] = s_;
        }
        // reduce over the 8 pixel-group lanes (width 8 within warp)
#pragma unroll
        for (int f = 0; f < 4; f++) {
#pragma unroll
            for (int off = 4; off; off >>= 1) {
                dt[f]  += __shfl_down_sync(0xffffffffu, dt[f],  off, 8);
                nr[f]  += __shfl_down_sync(0xffffffffu, nr[f],  off, 8);
                dsm[f] += __shfl_down_sync(0xffffffffu, dsm[f], off, 8);
            }
        }
        if (tx == 0) {
            float* gp = g_part + (size_t)(b * GX + bx) * 768 + c * 12;
#pragma unroll
            for (int f = 0; f < 4; f++) { gp[f] = dt[f]; gp[4+f] = nr[f]; gp[8+f] = dsm[f]; }
        }
    }
}

// ---------------------------------------------------------------------------
// K2: reduce 256 block-partials per (b,c), compute coefficients, fold weights.
// grid (C, B), 256 threads (one per bx).
// ---------------------------------------------------------------------------
__global__ __launch_bounds__(256) void k_reduce_coef(const float* __restrict__ origin_b,
                                                     const float* __restrict__ out_w) {
    const int c = blockIdx.x, b = blockIdx.y, tid = threadIdx.x;
    const float4* gp = (const float4*)(g_part + (size_t)(b * GX + tid) * 768 + c * 12);
    float4 a0 = gp[0], a1 = gp[1], a2 = gp[2];
    float v[12] = {a0.x,a0.y,a0.z,a0.w, a1.x,a1.y,a1.z,a1.w, a2.x,a2.y,a2.z,a2.w};

    const int lane = tid & 31, wrp = tid >> 5;
#pragma unroll
    for (int s = 0; s < 12; s++)
#pragma unroll
        for (int off = 16; off; off >>= 1)
            v[s] += __shfl_down_sync(0xffffffffu, v[s], off);

    __shared__ float red[8][12];
    if (lane == 0) {
#pragma unroll
        for (int s = 0; s < 12; s++) red[wrp][s] = v[s];
    }
    __syncthreads();

    if (tid == 0) {
        float st[12];
#pragma unroll
        for (int s = 0; s < 12; s++) {
            float t = 0.f;
#pragma unroll
            for (int w = 0; w < 8; w++) t += red[w][s];
            st[s] = t;
        }
        float w1 = out_w[c], w2 = out_w[CC + c], ob = origin_b[c];
        float ssum = 0.f;
#pragma unroll
        for (int f = 0; f < 4; f++) {
            float dtot = st[f] + ob * st[8 + f];
            float den  = fmaxf(sqrtf(st[4 + f]), 1e-12f);
            float coef = dtot / (den * den);
            g_A[(b * NFR + f) * CC + c] = -w1 * coef;
            ssum += coef;
        }
        g_A[(b * NFR + 4) * CC + c] = w2 + w1 * ssum;
    }
}

// ---------------------------------------------------------------------------
// K3: per-frame partial GEMV. grid (HW/512, B, NF) = 1280 blocks for occupancy.
// Explicit 8-deep load batches force MLP=8 (register-held float4s).
// ---------------------------------------------------------------------------
__global__ __launch_bounds__(128) void k_final_part(const float* __restrict__ inp) {
    __shared__ float sA[CC];
    const int f = blockIdx.z, b = blockIdx.y, tid = threadIdx.x;
    if (tid < CC) sA[tid] = g_A[(b * NFR + f) * CC + tid];
    __syncthreads();

    const int p = blockIdx.x * 512 + tid * 4;
    const float* base = inp + (size_t)((f * BB + b) * CC) * HW + p;
    float4 acc = make_float4(0.f, 0.f, 0.f, 0.f);
    for (int cc = 0; cc < CC; cc += 8) {
        float4 v[8];
#pragma unroll
        for (int i = 0; i < 8; i++) v[i] = *(const float4*)(base + (size_t)(cc + i) * HW);
#pragma unroll
        for (int i = 0; i < 8; i++) {
            float a = sA[cc + i];
            acc.x += a * v[i].x; acc.y += a * v[i].y;
            acc.z += a * v[i].z; acc.w += a * v[i].w;
        }
    }
    *(float4*)(g_yp + (size_t)(f * BB + b) * HW + p) = acc;
}

// ---------------------------------------------------------------------------
// K4: combine frame partials + bias.
// ---------------------------------------------------------------------------
__global__ __launch_bounds__(256) void k_combine(const float* __restrict__ out_b,
                                                 float* __restrict__ y) {
    const int i = blockIdx.x * 256 + threadIdx.x;   // float4 index over B*HW/4
    float ob = out_b[0];
    float4 acc = make_float4(ob, ob, ob, ob);
    const float4* yp = (const float4*)g_yp;
#pragma unroll
    for (int f = 0; f < NFR; f++) {
        float4 v = yp[(size_t)f * (BB * HW / 4) + i];
        acc.x += v.x; acc.y += v.y; acc.z += v.z; acc.w += v.w;
    }
    ((float4*)y)[i] = acc;
}

// ---------------------------------------------------------------------------
extern "C" void kernel_launch(void* const* d_in, const int* in_sizes, int n_in,
                              void* d_out, int out_size) {
    const float* inp      = (const float*)d_in[0];
    const float* origin_w = (const float*)d_in[1];
    const float* origin_b = (const float*)d_in[2];
    const float* out_w    = (const float*)d_in[3];
    const float* out_b    = (const float*)d_in[4];
    float* y = (float*)d_out;

    const int SMEM = KK * TPX * 4 + 2 * 32 * 65 * 8;   // 115200 B
    static int inited = 0;
    if (!inited) {
        cudaFuncSetAttribute(k_origin_fused, cudaFuncAttributeMaxDynamicSharedMemorySize, SMEM);
        inited = 1;
    }

    k_origin_fused<<<dim3(GX, BB), 128, SMEM>>>(inp, origin_w);
    k_reduce_coef <<<dim3(CC, BB), 256>>>(origin_b, out_w);
    k_final_part  <<<dim3(HW / 512, BB, NFR), 128>>>(inp);
    k_combine     <<<(BB * HW / 4) / 256, 256>>>(out_b, y);
}

// round 4
// speedup vs baseline: 1.2907x; 1.2907x over previous
#include <cuda_runtime.h>
#include <math.h>

#define NFR 5
#define BB  8
#define CC  64
#define HW  16384
#define KK  320
#define TP  128          // pixels per k_origin block

typedef unsigned long long ull;

// Scratch (allocation-free rules)
__device__ __align__(16) float g_origin[(size_t)BB*CC*HW];   // 33.5 MB
__device__ float g_stats[BB*CC*12];
__device__ float g_A[BB*NFR*CC];
__device__ __align__(16) float g_yp[(size_t)NFR*BB*HW];

__device__ __forceinline__ void fma2(ull &d, ull a, ull b) {
    asm("fma.rn.f32x2 %0, %1, %2, %0;" : "+l"(d) : "l"(a), "l"(b));
}
__device__ __forceinline__ ull pack2(float x) {
    ull r; unsigned u = __float_as_uint(x);
    asm("mov.b64 %0, {%1, %1};" : "=l"(r) : "r"(u));
    return r;
}
__device__ __forceinline__ void cp16(void* s, const void* g){
    unsigned saddr = (unsigned)__cvta_generic_to_shared(s);
    asm volatile("cp.async.cg.shared.global [%0], [%1], 16;\n" :: "r"(saddr), "l"(g) : "memory");
}
__device__ __forceinline__ void cp_commit(){ asm volatile("cp.async.commit_group;\n" ::: "memory"); }
__device__ __forceinline__ void cp_wait0(){ asm volatile("cp.async.wait_group 0;\n" ::: "memory"); }

// ---------------------------------------------------------------------------
// K1: origin[b,c,p] = sum_k W[c,k]*x[b,k,p].  128 thr, 8ch x 8px per thread.
// cp.async double-buffered x tiles; packed-u64 W double buffer.
// smem = 2*16KB (xs) + 2*16.6KB (ws) = 66KB -> 3 CTA/SM.
// ---------------------------------------------------------------------------
__global__ __launch_bounds__(128, 3) void k_origin(const float* __restrict__ inp,
                                                   const float* __restrict__ origin_w) {
    extern __shared__ char smem_raw[];
    float* xs  = (float*)smem_raw;                          // [2][32][128]
    ull*   ws2 = (ull*)(smem_raw + 2*32*TP*4);              // [2][32][65]

    const int tid = threadIdx.x;
    const int b   = blockIdx.y;
    const int p0  = blockIdx.x * TP;
    const int ty  = tid >> 4;       // 0..7  channel group
    const int tx  = tid & 15;       // 0..15 pixel group
    const int c0  = ty * 8;
    const int pp0 = tx * 4;         // u64 index (pixels 8*tx..8*tx+7)
    const int kkx = tid & 31;
    const int wrp = tid >> 5;

    ull acc[8][4];
#pragma unroll
    for (int i = 0; i < 8; i++)
#pragma unroll
        for (int j = 0; j < 4; j++) acc[i][j] = 0ull;

    float wv[16];

    // prologue: stage chunk 0
#pragma unroll
    for (int it = 0; it < 16; it++) wv[it] = origin_w[(it*4 + wrp) * KK + kkx];
#pragma unroll
    for (int it = 0; it < 8; it++) {
        int e = it * 128 + tid;
        int row = e >> 5, col4 = e & 31;
        int f = row >> 6, cp = row & 63;
        cp16(xs + (size_t)row * TP + col4 * 4,
             inp + (size_t)((f * BB + b) * CC + cp) * HW + p0 + col4 * 4);
    }
    cp_commit();
#pragma unroll
    for (int it = 0; it < 16; it++) ws2[(size_t)kkx * 65 + (it*4 + wrp)] = pack2(wv[it]);
    cp_wait0();
    __syncthreads();

    int buf = 0;
    for (int ch = 0; ch < 10; ch++) {
        // issue next chunk's loads first (latency hidden behind compute)
        if (ch < 9) {
            const int kb = (ch + 1) * 32;
#pragma unroll
            for (int it = 0; it < 16; it++) wv[it] = origin_w[(it*4 + wrp) * KK + kb + kkx];
#pragma unroll
            for (int it = 0; it < 8; it++) {
                int e = it * 128 + tid;
                int row = e >> 5, col4 = e & 31;
                int k = kb + row;
                int f = k >> 6, cp = k & 63;
                cp16(xs + (size_t)(buf ^ 1) * 32 * TP + (size_t)row * TP + col4 * 4,
                     inp + (size_t)((f * BB + b) * CC + cp) * HW + p0 + col4 * 4);
            }
            cp_commit();
        }

        // compute current chunk
        const float* xbase = xs + (size_t)buf * 32 * TP;
        const ull* wbase = ws2 + (size_t)buf * 32 * 65;
#pragma unroll 4
        for (int kx = 0; kx < 32; kx++) {
            const ull* xrow = (const ull*)(xbase + kx * TP);
            ulonglong2 xa = *(const ulonglong2*)(xrow + pp0);
            ulonglong2 xb = *(const ulonglong2*)(xrow + pp0 + 2);
            const ull* wrow = wbase + kx * 65;
#pragma unroll
            for (int ci = 0; ci < 8; ci++) {
                ull ww = wrow[c0 + ci];
                fma2(acc[ci][0], ww, xa.x);
                fma2(acc[ci][1], ww, xa.y);
                fma2(acc[ci][2], ww, xb.x);
                fma2(acc[ci][3], ww, xb.y);
            }
        }

        if (ch < 9) {
            ull* wdst = ws2 + (size_t)(buf ^ 1) * 32 * 65;
#pragma unroll
            for (int it = 0; it < 16; it++) wdst[(size_t)kkx * 65 + (it*4 + wrp)] = pack2(wv[it]);
            cp_wait0();
        }
        __syncthreads();
        buf ^= 1;
    }

#pragma unroll
    for (int ci = 0; ci < 8; ci++) {
        float* outp = g_origin + (size_t)(b * CC + c0 + ci) * HW + p0 + tx * 8;
        *(ulonglong2*)outp       = make_ulonglong2(acc[ci][0], acc[ci][1]);
        *((ulonglong2*)outp + 1) = make_ulonglong2(acc[ci][2], acc[ci][3]);
    }
}

// ---------------------------------------------------------------------------
// K2: per (b,c,f): dot, nrm, dsum over 16384 pixels. grid (C,B), 256 thr.
// ---------------------------------------------------------------------------
__global__ __launch_bounds__(256) void k_stats(const float* __restrict__ inp) {
    const int b = blockIdx.y, c = blockIdx.x, tid = threadIdx.x;
    const float4* last = (const float4*)(inp + (size_t)((4 * BB + b) * CC + c) * HW);
    const float4* org  = (const float4*)(g_origin + (size_t)(b * CC + c) * HW);
    const float4* fr0 = (const float4*)(inp + (size_t)((0 * BB + b) * CC + c) * HW);
    const float4* fr1 = (const float4*)(inp + (size_t)((1 * BB + b) * CC + c) * HW);
    const float4* fr2 = (const float4*)(inp + (size_t)((2 * BB + b) * CC + c) * HW);
    const float4* fr3 = (const float4*)(inp + (size_t)((3 * BB + b) * CC + c) * HW);
    const float4* frs[4] = {fr0, fr1, fr2, fr3};

    float dot[4] = {0,0,0,0}, nrm[4] = {0,0,0,0}, dsm[4] = {0,0,0,0};

    for (int i = tid; i < HW / 4; i += 256) {
        float4 l = last[i], o = org[i];
#pragma unroll
        for (int f = 0; f < 4; f++) {
            float4 x = frs[f][i];
            float d0 = l.x - x.x, d1 = l.y - x.y, d2 = l.z - x.z, d3 = l.w - x.w;
            dot[f] += o.x * d0 + o.y * d1 + o.z * d2 + o.w * d3;
            nrm[f] += d0 * d0 + d1 * d1 + d2 * d2 + d3 * d3;
            dsm[f] += d0 + d1 + d2 + d3;
        }
    }

    float v[12];
#pragma unroll
    for (int f = 0; f < 4; f++) { v[f] = dot[f]; v[4+f] = nrm[f]; v[8+f] = dsm[f]; }

    const int lane = tid & 31, warp = tid >> 5;
#pragma unroll
    for (int s = 0; s < 12; s++)
#pragma unroll
        for (int o = 16; o > 0; o >>= 1)
            v[s] += __shfl_down_sync(0xffffffffu, v[s], o);

    __shared__ float red[8][12];
    if (lane == 0) {
#pragma unroll
        for (int s = 0; s < 12; s++) red[warp][s] = v[s];
    }
    __syncthreads();
    if (tid < 12) {
        float s = 0.f;
#pragma unroll
        for (int w = 0; w < 8; w++) s += red[w][tid];
        g_stats[(b * CC + c) * 12 + tid] = s;
    }
}

// ---------------------------------------------------------------------------
// K3: coefficients + fold out_w/origin_b into per-(b,f,c) GEMV weights A.
// ---------------------------------------------------------------------------
__global__ void k_coef(const float* __restrict__ origin_b,
                       const float* __restrict__ out_w) {
    int tid = threadIdx.x;
    if (tid >= BB * CC) return;
    int b = tid >> 6, c = tid & 63;
    float w1 = out_w[c], w2 = out_w[CC + c], ob = origin_b[c];
    const float* st = g_stats + (b * CC + c) * 12;
    float ssum = 0.f;
#pragma unroll
    for (int f = 0; f < 4; f++) {
        float dt   = st[f] + ob * st[8 + f];
        float den  = fmaxf(sqrtf(st[4 + f]), 1e-12f);
        float coef = dt / (den * den);
        g_A[(b * NFR + f) * CC + c] = -w1 * coef;
        ssum += coef;
    }
    g_A[(b * NFR + 4) * CC + c] = w2 + w1 * ssum;
}

// ---------------------------------------------------------------------------
// K4: per-frame partial GEMV (forced MLP=8). grid (HW/512, B, NF) = 1280 blocks.
// ---------------------------------------------------------------------------
__global__ __launch_bounds__(128) void k_final_part(const float* __restrict__ inp) {
    __shared__ float sA[CC];
    const int f = blockIdx.z, b = blockIdx.y, tid = threadIdx.x;
    if (tid < CC) sA[tid] = g_A[(b * NFR + f) * CC + tid];
    __syncthreads();

    const int p = blockIdx.x * 512 + tid * 4;
    const float* base = inp + (size_t)((f * BB + b) * CC) * HW + p;
    float4 acc = make_float4(0.f, 0.f, 0.f, 0.f);
    for (int cc = 0; cc < CC; cc += 8) {
        float4 v[8];
#pragma unroll
        for (int i = 0; i < 8; i++) v[i] = *(const float4*)(base + (size_t)(cc + i) * HW);
#pragma unroll
        for (int i = 0; i < 8; i++) {
            float a = sA[cc + i];
            acc.x += a * v[i].x; acc.y += a * v[i].y;
            acc.z += a * v[i].z; acc.w += a * v[i].w;
        }
    }
    *(float4*)(g_yp + (size_t)(f * BB + b) * HW + p) = acc;
}

// ---------------------------------------------------------------------------
// K5: combine frame partials + bias. 256 blocks x 128 thr, 1 float4/thread.
// ---------------------------------------------------------------------------
__global__ __launch_bounds__(128) void k_combine(const float* __restrict__ out_b,
                                                 float* __restrict__ y) {
    const int i = blockIdx.x * 128 + threadIdx.x;   // float4 index over B*HW/4
    float ob = out_b[0];
    float4 acc = make_float4(ob, ob, ob, ob);
    const float4* yp = (const float4*)g_yp;
#pragma unroll
    for (int f = 0; f < NFR; f++) {
        float4 v = yp[(size_t)f * (BB * HW / 4) + i];
        acc.x += v.x; acc.y += v.y; acc.z += v.z; acc.w += v.w;
    }
    ((float4*)y)[i] = acc;
}

// ---------------------------------------------------------------------------
extern "C" void kernel_launch(void* const* d_in, const int* in_sizes, int n_in,
                              void* d_out, int out_size) {
    const float* inp      = (const float*)d_in[0];
    const float* origin_w = (const float*)d_in[1];
    const float* origin_b = (const float*)d_in[2];
    const float* out_w    = (const float*)d_in[3];
    const float* out_b    = (const float*)d_in[4];
    float* y = (float*)d_out;

    const int SMEM = 2*32*TP*4 + 2*32*65*8;   // 66048 B
    static int inited = 0;
    if (!inited) {
        cudaFuncSetAttribute(k_origin, cudaFuncAttributeMaxDynamicSharedMemorySize, SMEM);
        inited = 1;
    }

    k_origin    <<<dim3(HW / TP, BB), 128, SMEM>>>(inp, origin_w);
    k_stats     <<<dim3(CC, BB), 256>>>(inp);
    k_coef      <<<1, 512>>>(origin_b, out_w);
    k_final_part<<<dim3(HW / 512, BB, NFR), 128>>>(inp);
    k_combine   <<<(BB * HW / 4) / 128, 128>>>(out_b, y);
}

// round 7
// speedup vs baseline: 1.9597x; 1.5183x over previous
#include <cuda_runtime.h>
#include <math.h>

#define NFR 5
#define BB  8
#define CC  64
#define HW  16384
#define KK  320
#define TPX 128            // pixels per fused block
#define GX  (HW/TPX)       // 128 blocks per batch

#define XSTR 140           // xs row stride in floats (conflict-free for B frags)
#define WSTR 72            // wbuf row stride in floats (conflict-free for A frags)
#define XS_FLOATS   (KK*XSTR)            // 44800
#define WBUF_FLOATS (2*32*WSTR)          // 4608
#define SRED_FLOATS (4*768)              // 3072
#define SMEM_FLOATS (XS_FLOATS + WBUF_FLOATS + SRED_FLOATS)
#define SMEM_BYTES  (SMEM_FLOATS*4)      // 209920

typedef unsigned long long ull;

__device__ float g_part[(size_t)BB*GX*768];
__device__ float g_A[BB*NFR*CC];
__device__ __align__(16) float g_yp[(size_t)NFR*BB*HW];

__device__ __forceinline__ void cp16(void* s, const void* g){
    unsigned saddr = (unsigned)__cvta_generic_to_shared(s);
    asm volatile("cp.async.cg.shared.global [%0], [%1], 16;\n" :: "r"(saddr), "l"(g) : "memory");
}
__device__ __forceinline__ void cp_commit(){ asm volatile("cp.async.commit_group;\n" ::: "memory"); }
__device__ __forceinline__ void cp_wait0(){ asm volatile("cp.async.wait_group 0;\n" ::: "memory"); }

__device__ __forceinline__ void mma_tf32(float c[4], unsigned a0, unsigned a1, unsigned a2,
                                         unsigned a3, unsigned b0, unsigned b1) {
    asm volatile("mma.sync.aligned.m16n8k8.row.col.f32.tf32.tf32.f32 "
                 "{%0,%1,%2,%3}, {%4,%5,%6,%7}, {%8,%9}, {%0,%1,%2,%3};"
                 : "+f"(c[0]), "+f"(c[1]), "+f"(c[2]), "+f"(c[3])
                 : "r"(a0), "r"(a1), "r"(a2), "r"(a3), "r"(b0), "r"(b1));
}

// ---------------------------------------------------------------------------
// Fused: origin GEMM on tensor cores (tf32) + difference-basis stats from the
// persistent smem image. 512 threads, warp grid 4m x 4n:
//   warp (wm,wn): M rows 16*wm..+15, pixels 32*wn..+31 (4 n-tiles of 8).
// Emits per-CTA partial (dot,nrm,dsum)[c][f] -> g_part.
// ---------------------------------------------------------------------------
__global__ __launch_bounds__(512, 1) void k_origin_fused(const float* __restrict__ inp,
                                                         const float* __restrict__ origin_w) {
    extern __shared__ float sm[];
    float* xs    = sm;                         // [320][XSTR]
    float* wbuf  = sm + XS_FLOATS;             // [2][32][WSTR]
    float* sredp = sm + XS_FLOATS + WBUF_FLOATS; // [4][768]

    const int tid  = threadIdx.x;
    const int b    = blockIdx.y, bx = blockIdx.x;
    const int p0   = bx * TPX;
    const int wid  = tid >> 5, lane = tid & 31;
    const int gid  = lane >> 2, tig = lane & 3;
    const int wm   = wid >> 2, wn = wid & 3;
    const int c0   = wm * 16, pb = wn * 32;
    const int cW   = tid >> 3;          // W loader: channel 0..63
    const int kW   = (tid & 7) * 4;     // W loader: k sub-offset

    float cf[4][4];
#pragma unroll
    for (int j = 0; j < 4; j++)
#pragma unroll
        for (int i = 0; i < 4; i++) cf[j][i] = 0.f;

    for (int i = tid; i < SRED_FLOATS; i += 512) sredp[i] = 0.f;

    // ---- prologue: chunk 0 ----
    float4 wreg = *(const float4*)(origin_w + cW * KK + kW);
#pragma unroll
    for (int it = 0; it < 2; it++) {
        int e = it * 512 + tid;
        int row = e >> 5, col4 = e & 31;
        int f = row >> 6, cp = row & 63;
        cp16(xs + (size_t)row * XSTR + col4 * 4,
             inp + (size_t)((f * BB + b) * CC + cp) * HW + p0 + col4 * 4);
    }
    cp_commit();
    wbuf[(kW + 0) * WSTR + cW] = wreg.x;
    wbuf[(kW + 1) * WSTR + cW] = wreg.y;
    wbuf[(kW + 2) * WSTR + cW] = wreg.z;
    wbuf[(kW + 3) * WSTR + cW] = wreg.w;
    cp_wait0();
    __syncthreads();

    for (int ch = 0; ch < 10; ch++) {
        float4 wnext;
        if (ch < 9) {
            const int kb = (ch + 1) * 32;
            wnext = *(const float4*)(origin_w + cW * KK + kb + kW);
#pragma unroll
            for (int it = 0; it < 2; it++) {
                int e = it * 512 + tid;
                int row = e >> 5, col4 = e & 31;
                int k = kb + row;
                int f = k >> 6, cp = k & 63;
                cp16(xs + (size_t)k * XSTR + col4 * 4,
                     inp + (size_t)((f * BB + b) * CC + cp) * HW + p0 + col4 * 4);
            }
            cp_commit();
        }

        const float* wb = wbuf + (ch & 1) * (32 * WSTR);
        const int kg = ch * 32;
#pragma unroll
        for (int ks = 0; ks < 4; ks++) {
            const int kk = ks * 8;
            unsigned a0 = __float_as_uint(wb[(kk + tig) * WSTR + c0 + gid]);
            unsigned a1 = __float_as_uint(wb[(kk + tig) * WSTR + c0 + gid + 8]);
            unsigned a2 = __float_as_uint(wb[(kk + tig + 4) * WSTR + c0 + gid]);
            unsigned a3 = __float_as_uint(wb[(kk + tig + 4) * WSTR + c0 + gid + 8]);
            const float* xr0 = xs + (size_t)(kg + kk + tig) * XSTR;
            const float* xr1 = xr0 + 4 * XSTR;
#pragma unroll
            for (int j = 0; j < 4; j++) {
                int p = pb + 8 * j + gid;
                unsigned b0 = __float_as_uint(xr0[p]);
                unsigned b1 = __float_as_uint(xr1[p]);
                mma_tf32(cf[j], a0, a1, a2, a3, b0, b1);
            }
        }

        if (ch < 9) {
            float* wd = wbuf + ((ch + 1) & 1) * (32 * WSTR);
            wd[(kW + 0) * WSTR + cW] = wnext.x;
            wd[(kW + 1) * WSTR + cW] = wnext.y;
            wd[(kW + 2) * WSTR + cW] = wnext.z;
            wd[(kW + 3) * WSTR + cW] = wnext.w;
            cp_wait0();
        }
        __syncthreads();
    }

    // ---- fused stats epilogue ----
#pragma unroll
    for (int rr = 0; rr < 2; rr++) {
        const int r = c0 + gid + rr * 8;
        float dt[4] = {0,0,0,0}, nr[4] = {0,0,0,0}, ds[4] = {0,0,0,0};
#pragma unroll
        for (int j = 0; j < 4; j++) {
            const int p = pb + 8 * j + 2 * tig;
            float2 l = *(const float2*)(xs + (size_t)(4 * CC + r) * XSTR + p);
            float o0 = cf[j][rr * 2 + 0];
            float o1 = cf[j][rr * 2 + 1];
#pragma unroll
            for (int f = 0; f < 4; f++) {
                float2 xf = *(const float2*)(xs + (size_t)(f * CC + r) * XSTR + p);
                float d0 = l.x - xf.x, d1 = l.y - xf.y;
                dt[f] += o0 * d0 + o1 * d1;
                nr[f] += d0 * d0 + d1 * d1;
                ds[f] += d0 + d1;
            }
        }
#pragma unroll
        for (int f = 0; f < 4; f++) {
            dt[f] += __shfl_xor_sync(0xffffffffu, dt[f], 1);
            dt[f] += __shfl_xor_sync(0xffffffffu, dt[f], 2);
            nr[f] += __shfl_xor_sync(0xffffffffu, nr[f], 1);
            nr[f] += __shfl_xor_sync(0xffffffffu, nr[f], 2);
            ds[f] += __shfl_xor_sync(0xffffffffu, ds[f], 1);
            ds[f] += __shfl_xor_sync(0xffffffffu, ds[f], 2);
        }
        if (tig == 0) {
            float* dp = sredp + wn * 768 + r * 12;
#pragma unroll
            for (int f = 0; f < 4; f++) { dp[f] = dt[f]; dp[4 + f] = nr[f]; dp[8 + f] = ds[f]; }
        }
    }
    __syncthreads();

    float* gp = g_part + (size_t)(b * GX + bx) * 768;
    for (int i = tid; i < 768; i += 512)
        gp[i] = sredp[i] + sredp[768 + i] + sredp[1536 + i] + sredp[2304 + i];
}

// ---------------------------------------------------------------------------
// Reduce 128 block-partials per (b,c), compute coefficients, fold weights.
// ---------------------------------------------------------------------------
__global__ __launch_bounds__(128) void k_reduce_coef(const float* __restrict__ origin_b,
                                                     const float* __restrict__ out_w) {
    const int c = blockIdx.x, b = blockIdx.y, tid = threadIdx.x;
    const float4* gp = (const float4*)(g_part + (size_t)(b * GX + tid) * 768 + c * 12);
    float4 a0 = gp[0], a1 = gp[1], a2 = gp[2];
    float v[12] = {a0.x,a0.y,a0.z,a0.w, a1.x,a1.y,a1.z,a1.w, a2.x,a2.y,a2.z,a2.w};

    const int lane = tid & 31, wrp = tid >> 5;
#pragma unroll
    for (int s = 0; s < 12; s++)
#pragma unroll
        for (int off = 16; off; off >>= 1)
            v[s] += __shfl_down_sync(0xffffffffu, v[s], off);

    __shared__ float red[4][12];
    if (lane == 0) {
#pragma unroll
        for (int s = 0; s < 12; s++) red[wrp][s] = v[s];
    }
    __syncthreads();

    if (tid == 0) {
        float st[12];
#pragma unroll
        for (int s = 0; s < 12; s++)
            st[s] = red[0][s] + red[1][s] + red[2][s] + red[3][s];
        float w1 = out_w[c], w2 = out_w[CC + c], ob = origin_b[c];
        float ssum = 0.f;
#pragma unroll
        for (int f = 0; f < 4; f++) {
            float dtot = st[f] + ob * st[8 + f];
            float den  = fmaxf(sqrtf(st[4 + f]), 1e-12f);
            float coef = dtot / (den * den);
            g_A[(b * NFR + f) * CC + c] = -w1 * coef;
            ssum += coef;
        }
        g_A[(b * NFR + 4) * CC + c] = w2 + w1 * ssum;
    }
}

// ---------------------------------------------------------------------------
// Per-frame partial GEMV (forced MLP=8). grid (HW/512, B, NF) = 1280 blocks.
// ---------------------------------------------------------------------------
__global__ __launch_bounds__(128) void k_final_part(const float* __restrict__ inp) {
    __shared__ float sA[CC];
    const int f = blockIdx.z, b = blockIdx.y, tid = threadIdx.x;
    if (tid < CC) sA[tid] = g_A[(b * NFR + f) * CC + tid];
    __syncthreads();

    const int p = blockIdx.x * 512 + tid * 4;
    const float* base = inp + (size_t)((f * BB + b) * CC) * HW + p;
    float4 acc = make_float4(0.f, 0.f, 0.f, 0.f);
    for (int cc = 0; cc < CC; cc += 8) {
        float4 v[8];
#pragma unroll
        for (int i = 0; i < 8; i++) v[i] = *(const float4*)(base + (size_t)(cc + i) * HW);
#pragma unroll
        for (int i = 0; i < 8; i++) {
            float a = sA[cc + i];
            acc.x += a * v[i].x; acc.y += a * v[i].y;
            acc.z += a * v[i].z; acc.w += a * v[i].w;
        }
    }
    *(float4*)(g_yp + (size_t)(f * BB + b) * HW + p) = acc;
}

// ---------------------------------------------------------------------------
// Combine frame partials + bias.
// ---------------------------------------------------------------------------
__global__ __launch_bounds__(128) void k_combine(const float* __restrict__ out_b,
                                                 float* __restrict__ y) {
    const int i = blockIdx.x * 128 + threadIdx.x;
    float ob = out_b[0];
    float4 acc = make_float4(ob, ob, ob, ob);
    const float4* yp = (const float4*)g_yp;
#pragma unroll
    for (int f = 0; f < NFR; f++) {
        float4 v = yp[(size_t)f * (BB * HW / 4) + i];
        acc.x += v.x; acc.y += v.y; acc.z += v.z; acc.w += v.w;
    }
    ((float4*)y)[i] = acc;
}

// ---------------------------------------------------------------------------
extern "C" void kernel_launch(void* const* d_in, const int* in_sizes, int n_in,
                              void* d_out, int out_size) {
    const float* inp      = (const float*)d_in[0];
    const float* origin_w = (const float*)d_in[1];
    const float* origin_b = (const float*)d_in[2];
    const float* out_w    = (const float*)d_in[3];
    const float* out_b    = (const float*)d_in[4];
    float* y = (float*)d_out;

    static int inited = 0;
    if (!inited) {
        cudaFuncSetAttribute(k_origin_fused, cudaFuncAttributeMaxDynamicSharedMemorySize, SMEM_BYTES);
        inited = 1;
    }

    k_origin_fused<<<dim3(GX, BB), 512, SMEM_BYTES>>>(inp, origin_w);
    k_reduce_coef <<<dim3(CC, BB), 128>>>(origin_b, out_w);
    k_final_part  <<<dim3(HW / 512, BB, NFR), 128>>>(inp);
    k_combine     <<<(BB * HW / 4) / 128, 128>>>(out_b, y);
}

// round 8
// speedup vs baseline: 2.3394x; 1.1938x over previous
#include <cuda_runtime.h>
#include <math.h>

#define NFR 5
#define BB  8
#define CC  64
#define HW  16384
#define KK  320
#define TPX 64             // pixels per fused block
#define GX  (HW/TPX)       // 256 blocks per batch

#define WSTR 72            // wbuf row stride (A-frag loads conflict-free: 8*tig+gid)
#define XS_FLOATS   (KK*TPX)          // 20480 (no padding; XOR swizzle)
#define WBUF_FLOATS (2*32*WSTR)       // 4608
#define SRED_FLOATS (2*768)           // 1536
#define SMEM_BYTES  ((XS_FLOATS+WBUF_FLOATS+SRED_FLOATS)*4)   // 106496 -> 2 CTA/SM

__device__ float g_wt[KK*CC];                      // transposed W: [k][c]
__device__ float g_part[(size_t)BB*GX*768];
__device__ float g_A[BB*NFR*CC];
__device__ __align__(16) float g_yp[(size_t)NFR*BB*HW];

__device__ __forceinline__ void cp16(void* s, const void* g){
    unsigned saddr = (unsigned)__cvta_generic_to_shared(s);
    asm volatile("cp.async.cg.shared.global [%0], [%1], 16;\n" :: "r"(saddr), "l"(g) : "memory");
}
__device__ __forceinline__ void cp_commit(){ asm volatile("cp.async.commit_group;\n" ::: "memory"); }
__device__ __forceinline__ void cp_wait0(){ asm volatile("cp.async.wait_group 0;\n" ::: "memory"); }

__device__ __forceinline__ void mma_tf32(float c[4], unsigned a0, unsigned a1, unsigned a2,
                                         unsigned a3, unsigned b0, unsigned b1) {
    asm volatile("mma.sync.aligned.m16n8k8.row.col.f32.tf32.tf32.f32 "
                 "{%0,%1,%2,%3}, {%4,%5,%6,%7}, {%8,%9}, {%0,%1,%2,%3};"
                 : "+f"(c[0]), "+f"(c[1]), "+f"(c[2]), "+f"(c[3])
                 : "r"(a0), "r"(a1), "r"(a2), "r"(a3), "r"(b0), "r"(b1));
}

// ---------------------------------------------------------------------------
// W transpose: g_wt[k*64+c] = origin_w[c*320+k]. 80 KB once, L2-resident after.
// ---------------------------------------------------------------------------
__global__ __launch_bounds__(256) void k_wt(const float* __restrict__ w) {
    int i = blockIdx.x * 256 + threadIdx.x;      // i = k*64 + c
    int k = i >> 6, c = i & 63;
    g_wt[i] = w[c * KK + k];
}

// ---------------------------------------------------------------------------
// Fused origin GEMM (tf32 MMA) + difference-basis stats.
// 256 threads = 8 warps: wm = wid>>1 (M rows 16*wm..+15), wn = wid&1 (32 px).
// X image: [320][64] floats, XOR-swizzled 16B units: unit = col4 ^ ((k&3)<<1).
// ---------------------------------------------------------------------------
__global__ __launch_bounds__(256, 2) void k_origin_fused(const float* __restrict__ inp) {
    extern __shared__ float sm[];
    float* xs   = sm;                              // [320][64] swizzled
    float* wbuf = sm + XS_FLOATS;                  // [2][32][WSTR]
    float* sred = sm + XS_FLOATS + WBUF_FLOATS;    // [2][768]

    const int tid  = threadIdx.x;
    const int b    = blockIdx.y, bx = blockIdx.x;
    const int p0   = bx * TPX;
    const int wid  = tid >> 5, lane = tid & 31;
    const int gid  = lane >> 2, tig = lane & 3;
    const int wm   = wid >> 1, wn = wid & 1;
    const int c0   = wm * 16, pb = wn * 32;

    float cf[4][4];
#pragma unroll
    for (int j = 0; j < 4; j++)
#pragma unroll
        for (int i = 0; i < 4; i++) cf[j][i] = 0.f;

    // B-fragment swizzled offsets (independent of k-chunk)
    int boff[4];
#pragma unroll
    for (int j = 0; j < 4; j++) {
        int p = pb + 8 * j + gid;
        boff[j] = ((((p >> 2) ^ (tig << 1)) << 2) + (p & 3));
    }

    // ---- prologue: stage chunk 0 (x + W) ----
#pragma unroll
    for (int it = 0; it < 2; it++) {
        int e = it * 256 + tid;
        int row = e >> 4, col4 = e & 15;
        int unit = col4 ^ ((row & 3) << 1);
        int f = row >> 6, cp = row & 63;
        cp16(xs + row * TPX + unit * 4,
             inp + (size_t)((f * BB + b) * CC + cp) * HW + p0 + col4 * 4);
    }
#pragma unroll
    for (int it = 0; it < 2; it++) {
        int e = it * 256 + tid;
        int krow = e >> 4, c4 = e & 15;
        cp16(wbuf + krow * WSTR + c4 * 4, g_wt + krow * 64 + c4 * 4);
    }
    cp_commit(); cp_wait0();
    __syncthreads();

    int buf = 0;
    for (int ch = 0; ch < 10; ch++) {
        if (ch < 9) {
            const int kb = (ch + 1) * 32;
#pragma unroll
            for (int it = 0; it < 2; it++) {
                int e = it * 256 + tid;
                int row = e >> 4, col4 = e & 15;
                int k = kb + row;
                int unit = col4 ^ ((k & 3) << 1);
                int f = k >> 6, cp = k & 63;
                cp16(xs + k * TPX + unit * 4,
                     inp + (size_t)((f * BB + b) * CC + cp) * HW + p0 + col4 * 4);
            }
            float* wd = wbuf + (buf ^ 1) * (32 * WSTR);
#pragma unroll
            for (int it = 0; it < 2; it++) {
                int e = it * 256 + tid;
                int krow = e >> 4, c4 = e & 15;
                cp16(wd + krow * WSTR + c4 * 4, g_wt + (kb + krow) * 64 + c4 * 4);
            }
            cp_commit();
        }

        const float* wb = wbuf + buf * (32 * WSTR);
        const int kg = ch * 32;
#pragma unroll
        for (int ks = 0; ks < 4; ks++) {
            const int kk = ks * 8;
            unsigned a0 = __float_as_uint(wb[(kk + tig) * WSTR + c0 + gid]);
            unsigned a1 = __float_as_uint(wb[(kk + tig) * WSTR + c0 + gid + 8]);
            unsigned a2 = __float_as_uint(wb[(kk + tig + 4) * WSTR + c0 + gid]);
            unsigned a3 = __float_as_uint(wb[(kk + tig + 4) * WSTR + c0 + gid + 8]);
            const float* xr0 = xs + (kg + kk + tig) * TPX;
            const float* xr1 = xr0 + 4 * TPX;
#pragma unroll
            for (int j = 0; j < 4; j++) {
                unsigned b0 = __float_as_uint(xr0[boff[j]]);
                unsigned b1 = __float_as_uint(xr1[boff[j]]);
                mma_tf32(cf[j], a0, a1, a2, a3, b0, b1);
            }
        }

        if (ch < 9) cp_wait0();
        __syncthreads();
        buf ^= 1;
    }

    // ---- fused stats epilogue (reads swizzled xs) ----
    int eoff[4];
#pragma unroll
    for (int j = 0; j < 4; j++) {
        int p = pb + 8 * j + 2 * tig;
        eoff[j] = ((((p >> 2) ^ ((gid & 3) << 1)) << 2) + (p & 3));
    }

#pragma unroll
    for (int rr = 0; rr < 2; rr++) {
        const int r = c0 + gid + rr * 8;
        const float* lr = xs + (4 * CC + r) * TPX;
        float dt[4] = {0,0,0,0}, nr[4] = {0,0,0,0}, ds[4] = {0,0,0,0};
#pragma unroll
        for (int j = 0; j < 4; j++) {
            float2 l = *(const float2*)(lr + eoff[j]);
            float o0 = cf[j][rr * 2 + 0];
            float o1 = cf[j][rr * 2 + 1];
#pragma unroll
            for (int f = 0; f < 4; f++) {
                float2 xf = *(const float2*)(xs + (f * CC + r) * TPX + eoff[j]);
                float d0 = l.x - xf.x, d1 = l.y - xf.y;
                dt[f] += o0 * d0 + o1 * d1;
                nr[f] += d0 * d0 + d1 * d1;
                ds[f] += d0 + d1;
            }
        }
#pragma unroll
        for (int f = 0; f < 4; f++) {
            dt[f] += __shfl_xor_sync(0xffffffffu, dt[f], 1);
            dt[f] += __shfl_xor_sync(0xffffffffu, dt[f], 2);
            nr[f] += __shfl_xor_sync(0xffffffffu, nr[f], 1);
            nr[f] += __shfl_xor_sync(0xffffffffu, nr[f], 2);
            ds[f] += __shfl_xor_sync(0xffffffffu, ds[f], 1);
            ds[f] += __shfl_xor_sync(0xffffffffu, ds[f], 2);
        }
        if (tig == 0) {
            float* dp = sred + wn * 768 + r * 12;
#pragma unroll
            for (int f = 0; f < 4; f++) { dp[f] = dt[f]; dp[4 + f] = nr[f]; dp[8 + f] = ds[f]; }
        }
    }
    __syncthreads();

    float* gp = g_part + (size_t)(b * GX + bx) * 768;
    for (int i = tid; i < 768; i += 256)
        gp[i] = sred[i] + sred[768 + i];
}

// ---------------------------------------------------------------------------
// Reduce 256 block-partials per (b,c), compute coefficients, fold weights.
// ---------------------------------------------------------------------------
__global__ __launch_bounds__(256) void k_reduce_coef(const float* __restrict__ origin_b,
                                                     const float* __restrict__ out_w) {
    const int c = blockIdx.x, b = blockIdx.y, tid = threadIdx.x;
    const float4* gp = (const float4*)(g_part + (size_t)(b * GX + tid) * 768 + c * 12);
    float4 a0 = gp[0], a1 = gp[1], a2 = gp[2];
    float v[12] = {a0.x,a0.y,a0.z,a0.w, a1.x,a1.y,a1.z,a1.w, a2.x,a2.y,a2.z,a2.w};

    const int lane = tid & 31, wrp = tid >> 5;
#pragma unroll
    for (int s = 0; s < 12; s++)
#pragma unroll
        for (int off = 16; off; off >>= 1)
            v[s] += __shfl_down_sync(0xffffffffu, v[s], off);

    __shared__ float red[8][12];
    if (lane == 0) {
#pragma unroll
        for (int s = 0; s < 12; s++) red[wrp][s] = v[s];
    }
    __syncthreads();

    if (tid == 0) {
        float st[12];
#pragma unroll
        for (int s = 0; s < 12; s++) {
            float t = 0.f;
#pragma unroll
            for (int w = 0; w < 8; w++) t += red[w][s];
            st[s] = t;
        }
        float w1 = out_w[c], w2 = out_w[CC + c], ob = origin_b[c];
        float ssum = 0.f;
#pragma unroll
        for (int f = 0; f < 4; f++) {
            float dtot = st[f] + ob * st[8 + f];
            float den  = fmaxf(sqrtf(st[4 + f]), 1e-12f);
            float coef = dtot / (den * den);
            g_A[(b * NFR + f) * CC + c] = -w1 * coef;
            ssum += coef;
        }
        g_A[(b * NFR + 4) * CC + c] = w2 + w1 * ssum;
    }
}

// ---------------------------------------------------------------------------
// Per-frame partial GEMV (forced MLP=8). grid (HW/512, B, NF) = 1280 blocks.
// ---------------------------------------------------------------------------
__global__ __launch_bounds__(128) void k_final_part(const float* __restrict__ inp) {
    __shared__ float sA[CC];
    const int f = blockIdx.z, b = blockIdx.y, tid = threadIdx.x;
    if (tid < CC) sA[tid] = g_A[(b * NFR + f) * CC + tid];
    __syncthreads();

    const int p = blockIdx.x * 512 + tid * 4;
    const float* base = inp + (size_t)((f * BB + b) * CC) * HW + p;
    float4 acc = make_float4(0.f, 0.f, 0.f, 0.f);
    for (int cc = 0; cc < CC; cc += 8) {
        float4 v[8];
#pragma unroll
        for (int i = 0; i < 8; i++) v[i] = *(const float4*)(base + (size_t)(cc + i) * HW);
#pragma unroll
        for (int i = 0; i < 8; i++) {
            float a = sA[cc + i];
            acc.x += a * v[i].x; acc.y += a * v[i].y;
            acc.z += a * v[i].z; acc.w += a * v[i].w;
        }
    }
    *(float4*)(g_yp + (size_t)(f * BB + b) * HW + p) = acc;
}

// ---------------------------------------------------------------------------
// Combine frame partials + bias.
// ---------------------------------------------------------------------------
__global__ __launch_bounds__(128) void k_combine(const float* __restrict__ out_b,
                                                 float* __restrict__ y) {
    const int i = blockIdx.x * 128 + threadIdx.x;
    float ob = out_b[0];
    float4 acc = make_float4(ob, ob, ob, ob);
    const float4* yp = (const float4*)g_yp;
#pragma unroll
    for (int f = 0; f < NFR; f++) {
        float4 v = yp[(size_t)f * (BB * HW / 4) + i];
        acc.x += v.x; acc.y += v.y; acc.z += v.z; acc.w += v.w;
    }
    ((float4*)y)[i] = acc;
}

// ---------------------------------------------------------------------------
extern "C" void kernel_launch(void* const* d_in, const int* in_sizes, int n_in,
                              void* d_out, int out_size) {
    const float* inp      = (const float*)d_in[0];
    const float* origin_w = (const float*)d_in[1];
    const float* origin_b = (const float*)d_in[2];
    const float* out_w    = (const float*)d_in[3];
    const float* out_b    = (const float*)d_in[4];
    float* y = (float*)d_out;

    static int inited = 0;
    if (!inited) {
        cudaFuncSetAttribute(k_origin_fused, cudaFuncAttributeMaxDynamicSharedMemorySize, SMEM_BYTES);
        inited = 1;
    }

    k_wt          <<<KK * CC / 256, 256>>>(origin_w);
    k_origin_fused<<<dim3(GX, BB), 256, SMEM_BYTES>>>(inp);
    k_reduce_coef <<<dim3(CC, BB), 256>>>(origin_b, out_w);
    k_final_part  <<<dim3(HW / 512, BB, NFR), 128>>>(inp);
    k_combine     <<<(BB * HW / 4) / 128, 128>>>(out_b, y);
}

// round 9
// speedup vs baseline: 2.4004x; 1.0261x over previous
#include <cuda_runtime.h>
#include <math.h>

#define NFR 5
#define BB  8
#define CC  64
#define HW  16384
#define KK  320
#define TPX 64             // pixels per fused block
#define GX  (HW/TPX)       // 256 blocks per batch

#define WSTR 72            // wbuf row stride (A-frag loads conflict-free: 8*tig+gid)
#define XS_FLOATS   (KK*TPX)          // 20480 (no padding; XOR swizzle)
#define WBUF_FLOATS (2*32*WSTR)       // 4608
#define SRED_FLOATS (2*768)           // 1536
#define SMEM_BYTES  ((XS_FLOATS+WBUF_FLOATS+SRED_FLOATS)*4)   // 106496 -> 2 CTA/SM

__device__ float g_wt[KK*CC];                      // transposed W: [k][c]
__device__ float g_part[(size_t)BB*GX*768];
__device__ float g_A[BB*NFR*CC];
__device__ __align__(16) float g_yp[(size_t)NFR*BB*HW];

__device__ __forceinline__ void cp16(void* s, const void* g){
    unsigned saddr = (unsigned)__cvta_generic_to_shared(s);
    asm volatile("cp.async.cg.shared.global [%0], [%1], 16;\n" :: "r"(saddr), "l"(g) : "memory");
}
__device__ __forceinline__ void cp_commit(){ asm volatile("cp.async.commit_group;\n" ::: "memory"); }
__device__ __forceinline__ void cp_wait_n(int n){
    switch (n) {                    // fully-unrolled caller -> constant-folds to one instr
        case 0: asm volatile("cp.async.wait_group 0;" ::: "memory"); break;
        case 1: asm volatile("cp.async.wait_group 1;" ::: "memory"); break;
        case 2: asm volatile("cp.async.wait_group 2;" ::: "memory"); break;
        case 3: asm volatile("cp.async.wait_group 3;" ::: "memory"); break;
        case 4: asm volatile("cp.async.wait_group 4;" ::: "memory"); break;
        case 5: asm volatile("cp.async.wait_group 5;" ::: "memory"); break;
        case 6: asm volatile("cp.async.wait_group 6;" ::: "memory"); break;
        case 7: asm volatile("cp.async.wait_group 7;" ::: "memory"); break;
        case 8: asm volatile("cp.async.wait_group 8;" ::: "memory"); break;
        default: asm volatile("cp.async.wait_group 9;" ::: "memory"); break;
    }
}

__device__ __forceinline__ void mma_tf32(float c[4], unsigned a0, unsigned a1, unsigned a2,
                                         unsigned a3, unsigned b0, unsigned b1) {
    asm volatile("mma.sync.aligned.m16n8k8.row.col.f32.tf32.tf32.f32 "
                 "{%0,%1,%2,%3}, {%4,%5,%6,%7}, {%8,%9}, {%0,%1,%2,%3};"
                 : "+f"(c[0]), "+f"(c[1]), "+f"(c[2]), "+f"(c[3])
                 : "r"(a0), "r"(a1), "r"(a2), "r"(a3), "r"(b0), "r"(b1));
}

// ---------------------------------------------------------------------------
// W transpose: g_wt[k*64+c] = origin_w[c*320+k]. 80 KB once, L2-resident after.
// ---------------------------------------------------------------------------
__global__ __launch_bounds__(256) void k_wt(const float* __restrict__ w) {
    int i = blockIdx.x * 256 + threadIdx.x;      // i = k*64 + c
    int k = i >> 6, c = i & 63;
    g_wt[i] = w[c * KK + k];
}

// ---------------------------------------------------------------------------
// Fused origin GEMM (tf32 MMA) + difference-basis stats.
// Deep pipeline: ALL 10 X-chunk cp.async groups issued in the prologue
// (xs is persistent anyway), drained with wait_group(8-ch) per chunk.
// W: LDG->reg->STS double buffer (off the cp.async ordering).
// ---------------------------------------------------------------------------
__global__ __launch_bounds__(256, 2) void k_origin_fused(const float* __restrict__ inp) {
    extern __shared__ float sm[];
    float* xs   = sm;                              // [320][64] swizzled
    float* wbuf = sm + XS_FLOATS;                  // [2][32][WSTR]
    float* sred = sm + XS_FLOATS + WBUF_FLOATS;    // [2][768]

    const int tid  = threadIdx.x;
    const int b    = blockIdx.y, bx = blockIdx.x;
    const int p0   = bx * TPX;
    const int wid  = tid >> 5, lane = tid & 31;
    const int gid  = lane >> 2, tig = lane & 3;
    const int wm   = wid >> 1, wn = wid & 1;
    const int c0   = wm * 16, pb = wn * 32;
    const int krW  = tid >> 3;          // W loader row 0..31
    const int c8   = (tid & 7) * 8;     // W loader col base

    float cf[4][4];
#pragma unroll
    for (int j = 0; j < 4; j++)
#pragma unroll
        for (int i = 0; i < 4; i++) cf[j][i] = 0.f;

    // B-fragment swizzled offsets (independent of k-chunk)
    int boff[4];
#pragma unroll
    for (int j = 0; j < 4; j++) {
        int p = pb + 8 * j + gid;
        boff[j] = ((((p >> 2) ^ (tig << 1)) << 2) + (p & 3));
    }

    // ---- prologue: issue ALL X chunk loads as 10 commit groups ----
#pragma unroll
    for (int ch = 0; ch < 10; ch++) {
#pragma unroll
        for (int it = 0; it < 2; it++) {
            int e = it * 256 + tid;
            int row = e >> 4, col4 = e & 15;
            int k = ch * 32 + row;
            int unit = col4 ^ ((k & 3) << 1);
            int f = k >> 6, cp = k & 63;
            cp16(xs + k * TPX + unit * 4,
                 inp + (size_t)((f * BB + b) * CC + cp) * HW + p0 + col4 * 4);
        }
        cp_commit();
    }

    // W chunk 0 via LDG->STS
    {
        float4 wa = *(const float4*)(g_wt + krW * 64 + c8);
        float4 wb4 = *(const float4*)(g_wt + krW * 64 + c8 + 4);
        *(float4*)(wbuf + krW * WSTR + c8)     = wa;
        *(float4*)(wbuf + krW * WSTR + c8 + 4) = wb4;
    }
    cp_wait_n(9);            // X chunk 0 resident
    __syncthreads();

#pragma unroll
    for (int ch = 0; ch < 10; ch++) {
        float4 wna, wnb;
        if (ch < 9) {
            const float* wsrc = g_wt + (ch + 1) * 32 * 64 + krW * 64 + c8;
            wna = *(const float4*)(wsrc);
            wnb = *(const float4*)(wsrc + 4);
        }

        const float* wb = wbuf + (ch & 1) * (32 * WSTR);
        const int kg = ch * 32;
#pragma unroll
        for (int ks = 0; ks < 4; ks++) {
            const int kk = ks * 8;
            unsigned a0 = __float_as_uint(wb[(kk + tig) * WSTR + c0 + gid]);
            unsigned a1 = __float_as_uint(wb[(kk + tig) * WSTR + c0 + gid + 8]);
            unsigned a2 = __float_as_uint(wb[(kk + tig + 4) * WSTR + c0 + gid]);
            unsigned a3 = __float_as_uint(wb[(kk + tig + 4) * WSTR + c0 + gid + 8]);
            const float* xr0 = xs + (kg + kk + tig) * TPX;
            const float* xr1 = xr0 + 4 * TPX;
#pragma unroll
            for (int j = 0; j < 4; j++) {
                unsigned b0 = __float_as_uint(xr0[boff[j]]);
                unsigned b1 = __float_as_uint(xr1[boff[j]]);
                mma_tf32(cf[j], a0, a1, a2, a3, b0, b1);
            }
        }

        if (ch < 9) {
            float* wd = wbuf + ((ch + 1) & 1) * (32 * WSTR);
            *(float4*)(wd + krW * WSTR + c8)     = wna;
            *(float4*)(wd + krW * WSTR + c8 + 4) = wnb;
            cp_wait_n(8 - ch);     // X chunk ch+1 resident (had ~9 chunks of slack)
        }
        __syncthreads();
    }

    // ---- fused stats epilogue (reads swizzled xs) ----
    int eoff[4];
#pragma unroll
    for (int j = 0; j < 4; j++) {
        int p = pb + 8 * j + 2 * tig;
        eoff[j] = ((((p >> 2) ^ ((gid & 3) << 1)) << 2) + (p & 3));
    }

#pragma unroll
    for (int rr = 0; rr < 2; rr++) {
        const int r = c0 + gid + rr * 8;
        const float* lr = xs + (4 * CC + r) * TPX;
        float dt[4] = {0,0,0,0}, nr[4] = {0,0,0,0}, ds[4] = {0,0,0,0};
#pragma unroll
        for (int j = 0; j < 4; j++) {
            float2 l = *(const float2*)(lr + eoff[j]);
            float o0 = cf[j][rr * 2 + 0];
            float o1 = cf[j][rr * 2 + 1];
#pragma unroll
            for (int f = 0; f < 4; f++) {
                float2 xf = *(const float2*)(xs + (f * CC + r) * TPX + eoff[j]);
                float d0 = l.x - xf.x, d1 = l.y - xf.y;
                dt[f] += o0 * d0 + o1 * d1;
                nr[f] += d0 * d0 + d1 * d1;
                ds[f] += d0 + d1;
            }
        }
#pragma unroll
        for (int f = 0; f < 4; f++) {
            dt[f] += __shfl_xor_sync(0xffffffffu, dt[f], 1);
            dt[f] += __shfl_xor_sync(0xffffffffu, dt[f], 2);
            nr[f] += __shfl_xor_sync(0xffffffffu, nr[f], 1);
            nr[f] += __shfl_xor_sync(0xffffffffu, nr[f], 2);
            ds[f] += __shfl_xor_sync(0xffffffffu, ds[f], 1);
            ds[f] += __shfl_xor_sync(0xffffffffu, ds[f], 2);
        }
        if (tig == 0) {
            float* dp = sred + wn * 768 + r * 12;
#pragma unroll
            for (int f = 0; f < 4; f++) { dp[f] = dt[f]; dp[4 + f] = nr[f]; dp[8 + f] = ds[f]; }
        }
    }
    __syncthreads();

    float* gp = g_part + (size_t)(b * GX + bx) * 768;
    for (int i = tid; i < 768; i += 256)
        gp[i] = sred[i] + sred[768 + i];
}

// ---------------------------------------------------------------------------
// Reduce 256 block-partials per (b,c), compute coefficients, fold weights.
// ---------------------------------------------------------------------------
__global__ __launch_bounds__(256) void k_reduce_coef(const float* __restrict__ origin_b,
                                                     const float* __restrict__ out_w) {
    const int c = blockIdx.x, b = blockIdx.y, tid = threadIdx.x;
    const float4* gp = (const float4*)(g_part + (size_t)(b * GX + tid) * 768 + c * 12);
    float4 a0 = gp[0], a1 = gp[1], a2 = gp[2];
    float v[12] = {a0.x,a0.y,a0.z,a0.w, a1.x,a1.y,a1.z,a1.w, a2.x,a2.y,a2.z,a2.w};

    const int lane = tid & 31, wrp = tid >> 5;
#pragma unroll
    for (int s = 0; s < 12; s++)
#pragma unroll
        for (int off = 16; off; off >>= 1)
            v[s] += __shfl_down_sync(0xffffffffu, v[s], off);

    __shared__ float red[8][12];
    if (lane == 0) {
#pragma unroll
        for (int s = 0; s < 12; s++) red[wrp][s] = v[s];
    }
    __syncthreads();

    if (tid == 0) {
        float st[12];
#pragma unroll
        for (int s = 0; s < 12; s++) {
            float t = 0.f;
#pragma unroll
            for (int w = 0; w < 8; w++) t += red[w][s];
            st[s] = t;
        }
        float w1 = out_w[c], w2 = out_w[CC + c], ob = origin_b[c];
        float ssum = 0.f;
#pragma unroll
        for (int f = 0; f < 4; f++) {
            float dtot = st[f] + ob * st[8 + f];
            float den  = fmaxf(sqrtf(st[4 + f]), 1e-12f);
            float coef = dtot / (den * den);
            g_A[(b * NFR + f) * CC + c] = -w1 * coef;
            ssum += coef;
        }
        g_A[(b * NFR + 4) * CC + c] = w2 + w1 * ssum;
    }
}

// ---------------------------------------------------------------------------
// Per-frame partial GEMV (forced MLP=8). grid (HW/512, B, NF) = 1280 blocks.
// ---------------------------------------------------------------------------
__global__ __launch_bounds__(128) void k_final_part(const float* __restrict__ inp) {
    __shared__ float sA[CC];
    const int f = blockIdx.z, b = blockIdx.y, tid = threadIdx.x;
    if (tid < CC) sA[tid] = g_A[(b * NFR + f) * CC + tid];
    __syncthreads();

    const int p = blockIdx.x * 512 + tid * 4;
    const float* base = inp + (size_t)((f * BB + b) * CC) * HW + p;
    float4 acc = make_float4(0.f, 0.f, 0.f, 0.f);
    for (int cc = 0; cc < CC; cc += 8) {
        float4 v[8];
#pragma unroll
        for (int i = 0; i < 8; i++) v[i] = *(const float4*)(base + (size_t)(cc + i) * HW);
#pragma unroll
        for (int i = 0; i < 8; i++) {
            float a = sA[cc + i];
            acc.x += a * v[i].x; acc.y += a * v[i].y;
            acc.z += a * v[i].z; acc.w += a * v[i].w;
        }
    }
    *(float4*)(g_yp + (size_t)(f * BB + b) * HW + p) = acc;
}

// ---------------------------------------------------------------------------
// Combine frame partials + bias. float2/thread, 512 blocks for occupancy.
// ---------------------------------------------------------------------------
__global__ __launch_bounds__(128) void k_combine(const float* __restrict__ out_b,
                                                 float* __restrict__ y) {
    const int i = blockIdx.x * 128 + threadIdx.x;   // float2 index over B*HW/2
    float ob = out_b[0];
    float2 acc = make_float2(ob, ob);
    const float2* yp = (const float2*)g_yp;
#pragma unroll
    for (int f = 0; f < NFR; f++) {
        float2 v = yp[(size_t)f * (BB * HW / 2) + i];
        acc.x += v.x; acc.y += v.y;
    }
    ((float2*)y)[i] = acc;
}

// ---------------------------------------------------------------------------
extern "C" void kernel_launch(void* const* d_in, const int* in_sizes, int n_in,
                              void* d_out, int out_size) {
    const float* inp      = (const float*)d_in[0];
    const float* origin_w = (const float*)d_in[1];
    const float* origin_b = (const float*)d_in[2];
    const float* out_w    = (const float*)d_in[3];
    const float* out_b    = (const float*)d_in[4];
    float* y = (float*)d_out;

    static int inited = 0;
    if (!inited) {
        cudaFuncSetAttribute(k_origin_fused, cudaFuncAttributeMaxDynamicSharedMemorySize, SMEM_BYTES);
        inited = 1;
    }

    k_wt          <<<KK * CC / 256, 256>>>(origin_w);
    k_origin_fused<<<dim3(GX, BB), 256, SMEM_BYTES>>>(inp);
    k_reduce_coef <<<dim3(CC, BB), 256>>>(origin_b, out_w);
    k_final_part  <<<dim3(HW / 512, BB, NFR), 128>>>(inp);
    k_combine     <<<(BB * HW / 2) / 128, 128>>>(out_b, y);
}